// round 8
// baseline (speedup 1.0000x reference)
#include <cuda_runtime.h>
#include <cstdint>

#define T_STEPS 1000
#define BATCH   2048
#define FEAT    40
#define H1      8
#define H2      6
#define G1      32
#define G2      24

#define CT      10
#define NCHUNK  (T_STEPS / CT)      // 100
#define SITES   (CT * FEAT / 4)     // 100 float4 per chunk

typedef unsigned long long u64;

// ---------------- helpers ----------------
__device__ __forceinline__ u64 pack2(float x, float y) {
    u64 r; asm("mov.b64 %0, {%1, %2};" : "=l"(r) : "f"(x), "f"(y)); return r;
}
__device__ __forceinline__ void unpack2(u64 v, float& x, float& y) {
    asm("mov.b64 {%0, %1}, %2;" : "=f"(x), "=f"(y) : "l"(v));
}
__device__ __forceinline__ u64 fma2(u64 a, u64 b, u64 c) {
    u64 d; asm("fma.rn.f32x2 %0, %1, %2, %3;" : "=l"(d) : "l"(a), "l"(b), "l"(c)); return d;
}
__device__ __forceinline__ u64 mul2(u64 a, u64 b) {
    u64 d; asm("mul.rn.f32x2 %0, %1, %2;" : "=l"(d) : "l"(a), "l"(b)); return d;
}
__device__ __forceinline__ u64 add2(u64 a, u64 b) {
    u64 d; asm("add.rn.f32x2 %0, %1, %2;" : "=l"(d) : "l"(a), "l"(b)); return d;
}
__device__ __forceinline__ u64 scale2(u64 v, float s) {
    float a, b; unpack2(v, a, b); return pack2(a * s, b * s);
}
__device__ __forceinline__ float hadd2(u64 v) {
    float a, b; unpack2(v, a, b); return a + b;
}
__device__ __forceinline__ float tanha(float x) {
    float r; asm("tanh.approx.f32 %0, %1;" : "=f"(r) : "f"(x)); return r;
}
__device__ __forceinline__ float shflf(float v, int src) {
    return __shfl_sync(0xffffffffu, v, src & 31);
}
__device__ __forceinline__ uint32_t smem_u32(const void* p) {
    uint32_t a;
    asm("{ .reg .u64 t; cvta.to.shared.u64 t, %1; cvt.u32.u64 %0, t; }" : "=r"(a) : "l"(p));
    return a;
}
__device__ __forceinline__ void cp_async16(uint32_t saddr, const void* gaddr) {
    asm volatile("cp.async.cg.shared.global [%0], [%1], 16;" :: "r"(saddr), "l"(gaddr));
}
__device__ __forceinline__ void cp_commit() {
    asm volatile("cp.async.commit_group;" ::: "memory");
}
template <int N>
__device__ __forceinline__ void cp_wait() {
    asm volatile("cp.async.wait_group %0;" :: "n"(N) : "memory");
}
#define BAR64() asm volatile("bar.sync 0, 64;" ::: "memory")

// ============================================================================
// consumer step: layer1(i) + layer2(i-1).
// h1 travels through registers+shfl; slab holds only x2 [0..7] and h2 [8..13].
// ============================================================================
template <int RD>
__device__ __forceinline__ void rec_step(
    float en, int lane, float gval,
    float (*slab)[16],
    const float* __restrict__ w1s,
    const u64* __restrict__ wi2p, const u64* __restrict__ wh2p, u64 bias2p,
    float cn1, float ca1, float cn2, float ca2,
    float& c1, float& c2,
    const float* __restrict__ h1b, float* __restrict__ h1n)
{
    constexpr int WR = RD ^ 1;

    // ---- layer1 MAC: scalar, 2 chains, h1 from registers ----
    float A = fmaf(w1s[0], h1b[0], gval);
    float B = w1s[1] * h1b[1];
    A = fmaf(w1s[2], h1b[2], A);
    B = fmaf(w1s[3], h1b[3], B);
    A = fmaf(w1s[4], h1b[4], A);
    B = fmaf(w1s[5], h1b[5], B);
    A = fmaf(w1s[6], h1b[6], A);
    B = fmaf(w1s[7], h1b[7], B);
    float g1 = A + B;

    // ---- layer2 MAC: x2(i-1), h2(i-2) from slab ----
    const ulonglong2* hp = reinterpret_cast<const ulonglong2*>(&slab[RD][0]);
    ulonglong2 x01 = hp[0], x23 = hp[1], h2a = hp[2];
    u64 h2b = reinterpret_cast<const u64*>(&slab[RD][0])[6];

    u64 P = fma2(x01.x, wi2p[0], bias2p);
    u64 Q = mul2(x01.y, wi2p[1]);
    P = fma2(x23.x, wi2p[2], P);
    Q = fma2(x23.y, wi2p[3], Q);
    P = fma2(h2a.x, wh2p[0], P);
    Q = fma2(h2a.y, wh2p[1], Q);
    P = fma2(h2b,   wh2p[2], P);
    float g2 = hadd2(add2(P, Q));

    // ---- activations ----
    float a1 = fmaf(cn1, tanha(g1), ca1);
    float a2 = fmaf(cn2, tanha(g2), ca2);

    // ---- gate gathers ----
    float f1 = shflf(a1, lane + 8);
    float i1 = shflf(a1, lane + 16);
    float o1 = shflf(a1, lane + 24);
    float f2 = shflf(a2, lane + 6);
    float i2 = shflf(a2, lane + 12);
    float o2 = shflf(a2, lane + 18);

    // ---- layer1 state (lanes 0..7) ----
    c1 = fmaf(f1, c1, a1 * i1);
    float h1v = o1 * tanha(c1);

    // broadcast h1 immediately (critical chain)
#pragma unroll
    for (int j = 0; j < H1; j++) h1n[j] = shflf(h1v, j);

    float x2v = tanha(h1v);

    // ---- layer2 state (lanes 0..5) ----
    c2 = en * fmaf(f2, c2, a2 * i2);
    float h2v = o2 * tanha(c2);

    if (lane < H1) slab[WR][lane]     = x2v;
    if (lane < H2) slab[WR][8 + lane] = h2v;
    __syncwarp();
}

// ============================================================================
// fused producer/consumer kernel: 1 block = 1 batch element, 2 warps.
// ============================================================================
__global__ void __launch_bounds__(64)
fused_pc(const float* __restrict__ x,
         const float* __restrict__ W_ih1,
         const float* __restrict__ W_hh1,
         const float* __restrict__ b_ih1,
         const float* __restrict__ b_hh1,
         const float* __restrict__ W_ih2,
         const float* __restrict__ W_hh2,
         const float* __restrict__ b_ih2,
         const float* __restrict__ b_hh2,
         const float* __restrict__ W_fc,
         const float* __restrict__ b_fc,
         float* __restrict__ out) {
    __shared__ __align__(16) float sgate[2][CT][G1];   // gate ring (pre-scaled)
    __shared__ __align__(16) float sx[2][CT][FEAT];    // x staging (cp.async)
    __shared__ __align__(16) float slab[2][16];        // x2 [0..7], h2 [8..13]

    int tid  = threadIdx.x;
    int lane = tid & 31;
    int wid  = tid >> 5;
    int b    = blockIdx.x;

    if (wid == 1) {
        // ======================= PRODUCER =======================
        int l = lane & 15, h = lane >> 4;
        int gA = l, gB = l + 16;
        float cmA = 0.5f;                     // gates 0..15: sigmoid
        float cmB = (l < 8) ? 1.0f : 0.5f;    // 16..23 tanh, 24..31 sigmoid

        u64 wA[FEAT / 2], wB[FEAT / 2];
        {
            const u64* wra = reinterpret_cast<const u64*>(W_ih1 + gA * FEAT);
            const u64* wrb = reinterpret_cast<const u64*>(W_ih1 + gB * FEAT);
#pragma unroll
            for (int p = 0; p < FEAT / 2; p++) {
                wA[p] = scale2(wra[p], cmA);
                wB[p] = scale2(wrb[p], cmB);
            }
        }
        float bA = cmA * (b_ih1[gA] + b_hh1[gA]);
        float bB = cmB * (b_ih1[gB] + b_hh1[gB]);

        const float4* xb = reinterpret_cast<const float4*>(x + (size_t)b * T_STEPS * FEAT);
        uint32_t sx0 = smem_u32(&sx[0][0][0]);
        uint32_t sx1 = smem_u32(&sx[1][0][0]);

        // issue chunk 0 and 1
#pragma unroll
        for (int i = 0; i < 4; i++) {
            int s = lane + 32 * i;
            if (s < SITES) cp_async16(sx0 + 16 * s, xb + s);
        }
        cp_commit();
#pragma unroll
        for (int i = 0; i < 4; i++) {
            int s = lane + 32 * i;
            if (s < SITES) cp_async16(sx1 + 16 * s, xb + SITES + s);
        }
        cp_commit();
        cp_wait<1>();
        __syncwarp();

        // compute gates chunk 0
        {
#pragma unroll
            for (int p = 0; p < 5; p++) {
                int r = 2 * p + h;
                const ulonglong2* xr = reinterpret_cast<const ulonglong2*>(&sx[0][r][0]);
                u64 a0 = pack2(bA, 0.f), a1 = 0ull;
                u64 b0 = pack2(bB, 0.f), b1 = 0ull;
#pragma unroll
                for (int q = 0; q < FEAT / 4; q++) {
                    ulonglong2 v = xr[q];
                    a0 = fma2(wA[2 * q],     v.x, a0);
                    a1 = fma2(wA[2 * q + 1], v.y, a1);
                    b0 = fma2(wB[2 * q],     v.x, b0);
                    b1 = fma2(wB[2 * q + 1], v.y, b1);
                }
                sgate[0][r][gA] = hadd2(add2(a0, a1));
                sgate[0][r][gB] = hadd2(add2(b0, b1));
            }
        }
        BAR64();

#pragma unroll 1
        for (int c = 0; c < NCHUNK; c++) {
            if (c + 1 < NCHUNK) {
                // issue chunk c+2 (clamped) into sx[c&1] (chunk c consumed)
                int c2i = (c + 2 < NCHUNK) ? c + 2 : NCHUNK - 1;
                uint32_t dst = (c & 1) ? sx1 : sx0;
#pragma unroll
                for (int i = 0; i < 4; i++) {
                    int s = lane + 32 * i;
                    if (s < SITES) cp_async16(dst + 16 * s, xb + c2i * SITES + s);
                }
                cp_commit();
                cp_wait<1>();      // chunk c+1 resident
                __syncwarp();

                float (*dstg)[G1] = sgate[(c + 1) & 1];
                const float (*src)[FEAT] = sx[(c + 1) & 1];
#pragma unroll
                for (int p = 0; p < 5; p++) {
                    int r = 2 * p + h;
                    const ulonglong2* xr = reinterpret_cast<const ulonglong2*>(&src[r][0]);
                    u64 a0 = pack2(bA, 0.f), a1 = 0ull;
                    u64 b0 = pack2(bB, 0.f), b1 = 0ull;
#pragma unroll
                    for (int q = 0; q < FEAT / 4; q++) {
                        ulonglong2 v = xr[q];
                        a0 = fma2(wA[2 * q],     v.x, a0);
                        a1 = fma2(wA[2 * q + 1], v.y, a1);
                        b0 = fma2(wB[2 * q],     v.x, b0);
                        b1 = fma2(wB[2 * q + 1], v.y, b1);
                    }
                    dstg[r][gA] = hadd2(add2(a0, a1));
                    dstg[r][gB] = hadd2(add2(b0, b1));
                }
            }
            BAR64();
        }
        cp_wait<0>();
    } else {
        // ======================= CONSUMER =======================
        bool t1 = ((lane >> 3) == 2);
        float cm1 = t1 ? 1.f : 0.5f, cn1 = t1 ? 1.f : 0.5f, ca1 = t1 ? 0.f : 0.5f;
        bool t2 = (lane >= 12 && lane < 18);
        float cm2 = t2 ? 1.f : 0.5f, cn2 = t2 ? 1.f : 0.5f, ca2 = t2 ? 0.f : 0.5f;

        float w1s[H1];
#pragma unroll
        for (int j = 0; j < H1; j++) w1s[j] = cm1 * W_hh1[lane * H1 + j];

        u64 wi2p[H1 / 2], wh2p[H2 / 2], bias2p = 0ull;
#pragma unroll
        for (int j = 0; j < H1 / 2; j++) wi2p[j] = 0ull;
#pragma unroll
        for (int j = 0; j < H2 / 2; j++) wh2p[j] = 0ull;
        if (lane < G2) {
#pragma unroll
            for (int j = 0; j < H1 / 2; j++)
                wi2p[j] = pack2(cm2 * W_ih2[lane * H1 + 2 * j], cm2 * W_ih2[lane * H1 + 2 * j + 1]);
#pragma unroll
            for (int j = 0; j < H2 / 2; j++)
                wh2p[j] = pack2(cm2 * W_hh2[lane * H2 + 2 * j], cm2 * W_hh2[lane * H2 + 2 * j + 1]);
            bias2p = pack2(cm2 * (b_ih2[lane] + b_hh2[lane]), 0.f);
        }

        if (lane < 16) slab[1][lane] = 0.f;
        float hA[H1], hB[H1];
#pragma unroll
        for (int j = 0; j < H1; j++) hA[j] = 0.f;
        float c1 = 0.f, c2 = 0.f;
        BAR64();

#pragma unroll 1
        for (int c = 0; c < NCHUNK; c++) {
            const float* gr = &sgate[c & 1][0][0];
            // hoist gate loads off the chain
            float gv[CT];
#pragma unroll
            for (int t = 0; t < CT; t++) gv[t] = gr[t * G1 + lane];

            float en0 = (c == 0) ? 0.f : 1.f;
            rec_step<1>(en0, lane, gv[0], slab, w1s, wi2p, wh2p, bias2p,
                        cn1, ca1, cn2, ca2, c1, c2, hA, hB);
            rec_step<0>(1.f, lane, gv[1], slab, w1s, wi2p, wh2p, bias2p,
                        cn1, ca1, cn2, ca2, c1, c2, hB, hA);
            rec_step<1>(1.f, lane, gv[2], slab, w1s, wi2p, wh2p, bias2p,
                        cn1, ca1, cn2, ca2, c1, c2, hA, hB);
            rec_step<0>(1.f, lane, gv[3], slab, w1s, wi2p, wh2p, bias2p,
                        cn1, ca1, cn2, ca2, c1, c2, hB, hA);
            rec_step<1>(1.f, lane, gv[4], slab, w1s, wi2p, wh2p, bias2p,
                        cn1, ca1, cn2, ca2, c1, c2, hA, hB);
            rec_step<0>(1.f, lane, gv[5], slab, w1s, wi2p, wh2p, bias2p,
                        cn1, ca1, cn2, ca2, c1, c2, hB, hA);
            rec_step<1>(1.f, lane, gv[6], slab, w1s, wi2p, wh2p, bias2p,
                        cn1, ca1, cn2, ca2, c1, c2, hA, hB);
            rec_step<0>(1.f, lane, gv[7], slab, w1s, wi2p, wh2p, bias2p,
                        cn1, ca1, cn2, ca2, c1, c2, hB, hA);
            rec_step<1>(1.f, lane, gv[8], slab, w1s, wi2p, wh2p, bias2p,
                        cn1, ca1, cn2, ca2, c1, c2, hA, hB);
            rec_step<0>(1.f, lane, gv[9], slab, w1s, wi2p, wh2p, bias2p,
                        cn1, ca1, cn2, ca2, c1, c2, hB, hA);
            BAR64();
        }

        // ---- epilogue: layer2(999) from slab[1] (x2(999), h2(998)) ----
        const ulonglong2* hp = reinterpret_cast<const ulonglong2*>(&slab[1][0]);
        ulonglong2 x01 = hp[0], x23 = hp[1], h2a = hp[2];
        u64 h2b = reinterpret_cast<const u64*>(&slab[1][0])[6];

        u64 P = fma2(x01.x, wi2p[0], bias2p);
        u64 Q = mul2(x01.y, wi2p[1]);
        P = fma2(x23.x, wi2p[2], P);
        Q = fma2(x23.y, wi2p[3], Q);
        P = fma2(h2a.x, wh2p[0], P);
        Q = fma2(h2a.y, wh2p[1], Q);
        P = fma2(h2b,   wh2p[2], P);
        float g2 = hadd2(add2(P, Q));

        float a2 = fmaf(cn2, tanha(g2), ca2);
        float f2 = shflf(a2, lane + 6);
        float i2 = shflf(a2, lane + 12);
        float o2 = shflf(a2, lane + 18);
        c2 = fmaf(f2, c2, a2 * i2);
        float tx = tanha(o2 * tanha(c2));   // tanh(h2(999)), valid lanes 0..5

        float s = b_fc[0];
#pragma unroll
        for (int j = 0; j < H2; j++)
            s = fmaf(shflf(tx, j), W_fc[j], s);
        if (lane == 0)
            out[b] = fmaf(0.5f, tanha(0.5f * s), 0.5f);
    }
}

// ============================================================================
extern "C" void kernel_launch(void* const* d_in, const int* in_sizes, int n_in,
                              void* d_out, int out_size) {
    const float* x     = (const float*)d_in[0];
    const float* W_ih1 = (const float*)d_in[1];
    const float* W_hh1 = (const float*)d_in[2];
    const float* b_ih1 = (const float*)d_in[3];
    const float* b_hh1 = (const float*)d_in[4];
    const float* W_ih2 = (const float*)d_in[5];
    const float* W_hh2 = (const float*)d_in[6];
    const float* b_ih2 = (const float*)d_in[7];
    const float* b_hh2 = (const float*)d_in[8];
    const float* W_fc  = (const float*)d_in[9];
    const float* b_fc  = (const float*)d_in[10];
    float* out = (float*)d_out;

    fused_pc<<<BATCH, 64>>>(x, W_ih1, W_hh1, b_ih1, b_hh1,
                            W_ih2, W_hh2, b_ih2, b_hh2, W_fc, b_fc, out);
}

// round 9
// speedup vs baseline: 1.0184x; 1.0184x over previous
#include <cuda_runtime.h>
#include <cstdint>

#define T_STEPS 1000
#define BATCH   2048
#define FEAT    40
#define H1      8
#define H2      6
#define G1      32
#define G2      24

#define CT      10
#define NCHUNK  (T_STEPS / CT)      // 100
#define SITES   (CT * FEAT / 4)     // 100 float4 per chunk

typedef unsigned long long u64;

// ---------------- helpers ----------------
__device__ __forceinline__ u64 pack2(float x, float y) {
    u64 r; asm("mov.b64 %0, {%1, %2};" : "=l"(r) : "f"(x), "f"(y)); return r;
}
__device__ __forceinline__ void unpack2(u64 v, float& x, float& y) {
    asm("mov.b64 {%0, %1}, %2;" : "=f"(x), "=f"(y) : "l"(v));
}
__device__ __forceinline__ u64 fma2(u64 a, u64 b, u64 c) {
    u64 d; asm("fma.rn.f32x2 %0, %1, %2, %3;" : "=l"(d) : "l"(a), "l"(b), "l"(c)); return d;
}
__device__ __forceinline__ u64 mul2(u64 a, u64 b) {
    u64 d; asm("mul.rn.f32x2 %0, %1, %2;" : "=l"(d) : "l"(a), "l"(b)); return d;
}
__device__ __forceinline__ u64 add2(u64 a, u64 b) {
    u64 d; asm("add.rn.f32x2 %0, %1, %2;" : "=l"(d) : "l"(a), "l"(b)); return d;
}
__device__ __forceinline__ float hadd2(u64 v) {
    float a, b; unpack2(v, a, b); return a + b;
}
__device__ __forceinline__ float tanha(float x) {
    float r; asm("tanh.approx.f32 %0, %1;" : "=f"(r) : "f"(x)); return r;
}
__device__ __forceinline__ float shflf(float v, int src) {
    return __shfl_sync(0xffffffffu, v, src & 31);
}
__device__ __forceinline__ uint32_t smem_u32(const void* p) {
    uint32_t a;
    asm("{ .reg .u64 t; cvta.to.shared.u64 t, %1; cvt.u32.u64 %0, t; }" : "=r"(a) : "l"(p));
    return a;
}
__device__ __forceinline__ void cp_async16(uint32_t saddr, const void* gaddr) {
    asm volatile("cp.async.cg.shared.global [%0], [%1], 16;" :: "r"(saddr), "l"(gaddr));
}
__device__ __forceinline__ void cp_commit() {
    asm volatile("cp.async.commit_group;" ::: "memory");
}
template <int N>
__device__ __forceinline__ void cp_wait() {
    asm volatile("cp.async.wait_group %0;" :: "n"(N) : "memory");
}
#define BAR64() asm volatile("bar.sync 0, 64;" ::: "memory")

// ============================================================================
// consumer step (identical math to the 320us best): layer1(i) + layer2(i-1).
// slab shs[2][24]: [0..7]=h1, [8..15]=x2, [16..21]=h2
// ============================================================================
template <int RD>
__device__ __forceinline__ void rec_step(
    float en, int lane, float gval,
    float (*shs)[24],
    const u64* __restrict__ w1p, const u64* __restrict__ wi2p,
    const u64* __restrict__ wh2p, u64 bias2p,
    float cn1, float ca1, float cn2, float ca2,
    float& c1, float& c2)
{
    constexpr int WR = RD ^ 1;

    const ulonglong2* hp = reinterpret_cast<const ulonglong2*>(&shs[RD][0]);
    ulonglong2 h01 = hp[0], h23 = hp[1];   // h1[0..7]
    ulonglong2 x01 = hp[2], x23 = hp[3];   // x2[0..7]
    ulonglong2 h2a = hp[4];                // h2[0..3]
    u64        h2b = reinterpret_cast<const u64*>(&shs[RD][0])[10];  // h2[4..5]

    // layer1: g1 = gval + h1 . w1
    u64 C = mul2(h01.x, w1p[0]);
    C = fma2(h01.y, w1p[1], C);
    u64 D = mul2(h23.x, w1p[2]);
    D = fma2(h23.y, w1p[3], D);
    float g1 = gval + hadd2(add2(C, D));

    // layer2: g2 = bias2 + x2 . wi2 + h2 . wh2
    u64 P = fma2(x01.x, wi2p[0], bias2p);
    u64 Q = mul2(x01.y, wi2p[1]);
    P = fma2(x23.x, wi2p[2], P);
    Q = fma2(x23.y, wi2p[3], Q);
    P = fma2(h2a.x, wh2p[0], P);
    Q = fma2(h2a.y, wh2p[1], Q);
    P = fma2(h2b,   wh2p[2], P);
    float g2 = hadd2(add2(P, Q));

    float a1 = fmaf(cn1, tanha(g1), ca1);
    float a2 = fmaf(cn2, tanha(g2), ca2);

    float f1 = shflf(a1, lane + 8);
    float i1 = shflf(a1, lane + 16);
    float o1 = shflf(a1, lane + 24);
    float f2 = shflf(a2, lane + 6);
    float i2 = shflf(a2, lane + 12);
    float o2 = shflf(a2, lane + 18);

    c1 = fmaf(f1, c1, a1 * i1);
    float h1v = o1 * tanha(c1);
    float x2v = tanha(h1v);

    c2 = en * fmaf(f2, c2, a2 * i2);
    float h2v = o2 * tanha(c2);

    if (lane < H1) {
        shs[WR][lane]     = h1v;
        shs[WR][8 + lane] = x2v;
    }
    if (lane < H2) shs[WR][16 + lane] = h2v;
    __syncwarp();
}

// ============================================================================
// fused producer/consumer: 1 block = 1 batch element, 2 warps.
// Producer weights live in smem (shared across grid semantics, per-block copy).
// ============================================================================
__global__ void __launch_bounds__(64, 14)
fused_pc(const float* __restrict__ x,
         const float* __restrict__ W_ih1,
         const float* __restrict__ W_hh1,
         const float* __restrict__ b_ih1,
         const float* __restrict__ b_hh1,
         const float* __restrict__ W_ih2,
         const float* __restrict__ W_hh2,
         const float* __restrict__ b_ih2,
         const float* __restrict__ b_hh2,
         const float* __restrict__ W_fc,
         const float* __restrict__ b_fc,
         float* __restrict__ out) {
    __shared__ __align__(16) float sgate[2][CT][G1];      // gate ring (pre-scaled)
    __shared__ __align__(16) float sx[2][CT][FEAT];       // x staging (cp.async)
    __shared__ __align__(16) float shs[2][24];            // h1/x2/h2 slabs
    __shared__ __align__(16) ulonglong2 sw[10][2][16];    // proj weights (pre-scaled)

    int tid  = threadIdx.x;
    int lane = tid & 31;
    int wid  = tid >> 5;
    int b    = blockIdx.x;

    // ---- cooperative producer-weight staging: sw[q][k][l] = (w pair 2q, pair 2q+1)
    // gate g = (k==0 ? l : l+16); pre-scaled by activation input scale.
    for (int e = tid; e < 320; e += 64) {
        int q = e >> 5, rem = e & 31, k = rem >> 4, l = rem & 15;
        int g = (k == 0) ? l : (l + 16);
        float cm = (g >= 16 && g < 24) ? 1.0f : 0.5f;
        const float* wr = W_ih1 + g * FEAT + 4 * q;
        ulonglong2 wv;
        wv.x = pack2(wr[0] * cm, wr[1] * cm);
        wv.y = pack2(wr[2] * cm, wr[3] * cm);
        sw[q][k][l] = wv;
    }
    if (tid < 24) shs[1][tid] = 0.f;   // zero state read by step 0 (covers lanes<16 too)

    if (wid == 1) {
        // ======================= PRODUCER =======================
        int l = lane & 15, h = lane >> 4;
        float bA = 0.5f * (b_ih1[l] + b_hh1[l]);
        float cmB = (l < 8) ? 1.0f : 0.5f;
        float bB = cmB * (b_ih1[l + 16] + b_hh1[l + 16]);

        const float4* xb = reinterpret_cast<const float4*>(x + (size_t)b * T_STEPS * FEAT);
        uint32_t sx0 = smem_u32(&sx[0][0][0]);
        uint32_t sx1 = smem_u32(&sx[1][0][0]);

        // issue chunks 0,1
#pragma unroll
        for (int i = 0; i < 4; i++) {
            int s = lane + 32 * i;
            if (s < SITES) cp_async16(sx0 + 16 * s, xb + s);
        }
        cp_commit();
#pragma unroll
        for (int i = 0; i < 4; i++) {
            int s = lane + 32 * i;
            if (s < SITES) cp_async16(sx1 + 16 * s, xb + SITES + s);
        }
        cp_commit();
        cp_wait<1>();
        __syncwarp();   // weights staged by this warp's own stores + sx ready

        // gates for chunk 0 (q-outer, 5-row accumulators)
        {
            u64 accA[5], accB[5];
#pragma unroll
            for (int r = 0; r < 5; r++) { accA[r] = pack2(bA, 0.f); accB[r] = pack2(bB, 0.f); }
#pragma unroll
            for (int q = 0; q < 10; q++) {
                ulonglong2 wa = sw[q][0][l];
                ulonglong2 wb = sw[q][1][l];
#pragma unroll
                for (int r = 0; r < 5; r++) {
                    const ulonglong2 v = *reinterpret_cast<const ulonglong2*>(&sx[0][2 * r + h][4 * q]);
                    accA[r] = fma2(wa.x, v.x, accA[r]);
                    accA[r] = fma2(wa.y, v.y, accA[r]);
                    accB[r] = fma2(wb.x, v.x, accB[r]);
                    accB[r] = fma2(wb.y, v.y, accB[r]);
                }
            }
#pragma unroll
            for (int r = 0; r < 5; r++) {
                sgate[0][2 * r + h][l]      = hadd2(accA[r]);
                sgate[0][2 * r + h][l + 16] = hadd2(accB[r]);
            }
        }
        BAR64();

#pragma unroll 1
        for (int c = 0; c < NCHUNK; c++) {
            if (c + 1 < NCHUNK) {
                int c2i = (c + 2 < NCHUNK) ? c + 2 : NCHUNK - 1;
                uint32_t dst = (c & 1) ? sx1 : sx0;
#pragma unroll
                for (int i = 0; i < 4; i++) {
                    int s = lane + 32 * i;
                    if (s < SITES) cp_async16(dst + 16 * s, xb + c2i * SITES + s);
                }
                cp_commit();
                cp_wait<1>();      // chunk c+1 resident
                __syncwarp();

                float (*dstg)[G1] = sgate[(c + 1) & 1];
                const float (*src)[FEAT] = sx[(c + 1) & 1];

                u64 accA[5], accB[5];
#pragma unroll
                for (int r = 0; r < 5; r++) { accA[r] = pack2(bA, 0.f); accB[r] = pack2(bB, 0.f); }
#pragma unroll
                for (int q = 0; q < 10; q++) {
                    ulonglong2 wa = sw[q][0][l];
                    ulonglong2 wb = sw[q][1][l];
#pragma unroll
                    for (int r = 0; r < 5; r++) {
                        const ulonglong2 v = *reinterpret_cast<const ulonglong2*>(&src[2 * r + h][4 * q]);
                        accA[r] = fma2(wa.x, v.x, accA[r]);
                        accA[r] = fma2(wa.y, v.y, accA[r]);
                        accB[r] = fma2(wb.x, v.x, accB[r]);
                        accB[r] = fma2(wb.y, v.y, accB[r]);
                    }
                }
#pragma unroll
                for (int r = 0; r < 5; r++) {
                    dstg[2 * r + h][l]      = hadd2(accA[r]);
                    dstg[2 * r + h][l + 16] = hadd2(accB[r]);
                }
            }
            BAR64();
        }
        cp_wait<0>();
    } else {
        // ======================= CONSUMER =======================
        bool t1 = ((lane >> 3) == 2);
        float cm1 = t1 ? 1.f : 0.5f, cn1 = t1 ? 1.f : 0.5f, ca1 = t1 ? 0.f : 0.5f;
        bool t2 = (lane >= 12 && lane < 18);
        float cm2 = t2 ? 1.f : 0.5f, cn2 = t2 ? 1.f : 0.5f, ca2 = t2 ? 0.f : 0.5f;

        u64 w1p[H1 / 2];
#pragma unroll
        for (int j = 0; j < H1 / 2; j++)
            w1p[j] = pack2(cm1 * W_hh1[lane * H1 + 2 * j], cm1 * W_hh1[lane * H1 + 2 * j + 1]);

        u64 wi2p[H1 / 2], wh2p[H2 / 2], bias2p = 0ull;
#pragma unroll
        for (int j = 0; j < H1 / 2; j++) wi2p[j] = 0ull;
#pragma unroll
        for (int j = 0; j < H2 / 2; j++) wh2p[j] = 0ull;
        if (lane < G2) {
#pragma unroll
            for (int j = 0; j < H1 / 2; j++)
                wi2p[j] = pack2(cm2 * W_ih2[lane * H1 + 2 * j], cm2 * W_ih2[lane * H1 + 2 * j + 1]);
#pragma unroll
            for (int j = 0; j < H2 / 2; j++)
                wh2p[j] = pack2(cm2 * W_hh2[lane * H2 + 2 * j], cm2 * W_hh2[lane * H2 + 2 * j + 1]);
            bias2p = pack2(cm2 * (b_ih2[lane] + b_hh2[lane]), 0.f);
        }

        float c1 = 0.f, c2 = 0.f;
        BAR64();

#pragma unroll 1
        for (int c = 0; c < NCHUNK; c++) {
            const float* gr = &sgate[c & 1][0][0];
            float en0 = (c == 0) ? 0.f : 1.f;

            rec_step<1>(en0, lane, gr[0 * G1 + lane], shs, w1p, wi2p, wh2p, bias2p,
                        cn1, ca1, cn2, ca2, c1, c2);
            rec_step<0>(1.f, lane, gr[1 * G1 + lane], shs, w1p, wi2p, wh2p, bias2p,
                        cn1, ca1, cn2, ca2, c1, c2);
            rec_step<1>(1.f, lane, gr[2 * G1 + lane], shs, w1p, wi2p, wh2p, bias2p,
                        cn1, ca1, cn2, ca2, c1, c2);
            rec_step<0>(1.f, lane, gr[3 * G1 + lane], shs, w1p, wi2p, wh2p, bias2p,
                        cn1, ca1, cn2, ca2, c1, c2);
            rec_step<1>(1.f, lane, gr[4 * G1 + lane], shs, w1p, wi2p, wh2p, bias2p,
                        cn1, ca1, cn2, ca2, c1, c2);
            rec_step<0>(1.f, lane, gr[5 * G1 + lane], shs, w1p, wi2p, wh2p, bias2p,
                        cn1, ca1, cn2, ca2, c1, c2);
            rec_step<1>(1.f, lane, gr[6 * G1 + lane], shs, w1p, wi2p, wh2p, bias2p,
                        cn1, ca1, cn2, ca2, c1, c2);
            rec_step<0>(1.f, lane, gr[7 * G1 + lane], shs, w1p, wi2p, wh2p, bias2p,
                        cn1, ca1, cn2, ca2, c1, c2);
            rec_step<1>(1.f, lane, gr[8 * G1 + lane], shs, w1p, wi2p, wh2p, bias2p,
                        cn1, ca1, cn2, ca2, c1, c2);
            rec_step<0>(1.f, lane, gr[9 * G1 + lane], shs, w1p, wi2p, wh2p, bias2p,
                        cn1, ca1, cn2, ca2, c1, c2);
            BAR64();
        }

        // ---- epilogue: layer2(999) from shs[1] (x2(999), h2(998)) ----
        const ulonglong2* hp = reinterpret_cast<const ulonglong2*>(&shs[1][0]);
        ulonglong2 x01 = hp[2], x23 = hp[3], h2a = hp[4];
        u64 h2b = reinterpret_cast<const u64*>(&shs[1][0])[10];

        u64 P = fma2(x01.x, wi2p[0], bias2p);
        u64 Q = mul2(x01.y, wi2p[1]);
        P = fma2(x23.x, wi2p[2], P);
        Q = fma2(x23.y, wi2p[3], Q);
        P = fma2(h2a.x, wh2p[0], P);
        Q = fma2(h2a.y, wh2p[1], Q);
        P = fma2(h2b,   wh2p[2], P);
        float g2 = hadd2(add2(P, Q));

        float a2 = fmaf(cn2, tanha(g2), ca2);
        float f2 = shflf(a2, lane + 6);
        float i2 = shflf(a2, lane + 12);
        float o2 = shflf(a2, lane + 18);
        c2 = fmaf(f2, c2, a2 * i2);
        float tx = tanha(o2 * tanha(c2));   // tanh(h2(999)), valid lanes 0..5

        float s = b_fc[0];
#pragma unroll
        for (int j = 0; j < H2; j++)
            s = fmaf(shflf(tx, j), W_fc[j], s);
        if (lane == 0)
            out[b] = fmaf(0.5f, tanha(0.5f * s), 0.5f);
    }
}

// ============================================================================
extern "C" void kernel_launch(void* const* d_in, const int* in_sizes, int n_in,
                              void* d_out, int out_size) {
    const float* x     = (const float*)d_in[0];
    const float* W_ih1 = (const float*)d_in[1];
    const float* W_hh1 = (const float*)d_in[2];
    const float* b_ih1 = (const float*)d_in[3];
    const float* b_hh1 = (const float*)d_in[4];
    const float* W_ih2 = (const float*)d_in[5];
    const float* W_hh2 = (const float*)d_in[6];
    const float* b_ih2 = (const float*)d_in[7];
    const float* b_hh2 = (const float*)d_in[8];
    const float* W_fc  = (const float*)d_in[9];
    const float* b_fc  = (const float*)d_in[10];
    float* out = (float*)d_out;

    fused_pc<<<BATCH, 64>>>(x, W_ih1, W_hh1, b_ih1, b_hh1,
                            W_ih2, W_hh2, b_ih2, b_hh2, W_fc, b_fc, out);
}

// round 10
// speedup vs baseline: 1.1199x; 1.0997x over previous
#include <cuda_runtime.h>
#include <cstdint>

#define T_STEPS 1000
#define BATCH   2048
#define FEAT    40
#define H1      8
#define H2      6
#define G1      32
#define G2      24

#define CT      10
#define NCHUNK  (T_STEPS / CT)      // 100
#define SITES   (CT * FEAT / 4)     // 100 float4 per chunk

typedef unsigned long long u64;

// ---------------- helpers ----------------
__device__ __forceinline__ u64 pack2(float x, float y) {
    u64 r; asm("mov.b64 %0, {%1, %2};" : "=l"(r) : "f"(x), "f"(y)); return r;
}
__device__ __forceinline__ void unpack2(u64 v, float& x, float& y) {
    asm("mov.b64 {%0, %1}, %2;" : "=f"(x), "=f"(y) : "l"(v));
}
__device__ __forceinline__ u64 fma2(u64 a, u64 b, u64 c) {
    u64 d; asm("fma.rn.f32x2 %0, %1, %2, %3;" : "=l"(d) : "l"(a), "l"(b), "l"(c)); return d;
}
__device__ __forceinline__ u64 mul2(u64 a, u64 b) {
    u64 d; asm("mul.rn.f32x2 %0, %1, %2;" : "=l"(d) : "l"(a), "l"(b)); return d;
}
__device__ __forceinline__ u64 add2(u64 a, u64 b) {
    u64 d; asm("add.rn.f32x2 %0, %1, %2;" : "=l"(d) : "l"(a), "l"(b)); return d;
}
__device__ __forceinline__ u64 scale2(u64 v, float s) {
    float a, b; unpack2(v, a, b); return pack2(a * s, b * s);
}
__device__ __forceinline__ float hadd2(u64 v) {
    float a, b; unpack2(v, a, b); return a + b;
}
__device__ __forceinline__ float tanha(float x) {
    float r; asm("tanh.approx.f32 %0, %1;" : "=f"(r) : "f"(x)); return r;
}
__device__ __forceinline__ float shflf(float v, int src) {
    return __shfl_sync(0xffffffffu, v, src & 31);
}
__device__ __forceinline__ float shflx(float v, int m) {
    return __shfl_xor_sync(0xffffffffu, v, m);
}
__device__ __forceinline__ uint32_t smem_u32(const void* p) {
    uint32_t a;
    asm("{ .reg .u64 t; cvta.to.shared.u64 t, %1; cvt.u32.u64 %0, t; }" : "=r"(a) : "l"(p));
    return a;
}
__device__ __forceinline__ void cp_async16(uint32_t saddr, const void* gaddr) {
    asm volatile("cp.async.cg.shared.global [%0], [%1], 16;" :: "r"(saddr), "l"(gaddr));
}
__device__ __forceinline__ void cp_commit() {
    asm volatile("cp.async.commit_group;" ::: "memory");
}
template <int N>
__device__ __forceinline__ void cp_wait() {
    asm volatile("cp.async.wait_group %0;" :: "n"(N) : "memory");
}
#define BAR64() asm volatile("bar.sync 0, 64;" ::: "memory")

// ============================================================================
// consumer step: layer1(i) + layer2(i-1); XOR-shuffle gate gathering.
// slab shs[2][24]: [0..7]=h1, [8..15]=x2, [16..21]=h2
// L1 gates at lanes: i 0-7 | f 8-15 | g 16-23 | o 24-31  (c1 lives on lanes 8-15)
// L2 gates at lanes: i 0-5 | f 8-13 | g 16-21 | o 24-29  (c2 lives on lanes 8-13)
// ============================================================================
template <int RD>
__device__ __forceinline__ void rec_step(
    float en, int lane, float gval,
    float (*shs)[24],
    const u64* __restrict__ w1p, const u64* __restrict__ wi2p,
    const u64* __restrict__ wh2p, u64 bias2p,
    float cn1, float ca1, float cn2, float ca2,
    float& c1, float& c2)
{
    constexpr int WR = RD ^ 1;

    const ulonglong2* hp = reinterpret_cast<const ulonglong2*>(&shs[RD][0]);
    ulonglong2 h01 = hp[0], h23 = hp[1];   // h1[0..7]
    ulonglong2 x01 = hp[2], x23 = hp[3];   // x2[0..7]
    ulonglong2 h2a = hp[4];                // h2[0..3]
    u64        h2b = reinterpret_cast<const u64*>(&shs[RD][0])[10];  // h2[4..5]

    // layer1: g1 = gval + h1 . w1
    u64 C = mul2(h01.x, w1p[0]);
    C = fma2(h01.y, w1p[1], C);
    u64 D = mul2(h23.x, w1p[2]);
    D = fma2(h23.y, w1p[3], D);
    float g1 = gval + hadd2(add2(C, D));

    // layer2: g2 = bias2 + x2 . wi2 + h2 . wh2
    u64 P = fma2(x01.x, wi2p[0], bias2p);
    u64 Q = mul2(x01.y, wi2p[1]);
    P = fma2(x23.x, wi2p[2], P);
    Q = fma2(x23.y, wi2p[3], Q);
    P = fma2(h2a.x, wh2p[0], P);
    Q = fma2(h2a.y, wh2p[1], Q);
    P = fma2(h2b,   wh2p[2], P);
    float g2 = hadd2(add2(P, Q));

    float a1 = fmaf(cn1, tanha(g1), ca1);
    float a2 = fmaf(cn2, tanha(g2), ca2);

    // XOR gathers: s carries (g | o | i | f) partner; p = i*g on low quarter
    float s1 = shflx(a1, 16);
    float s2 = shflx(a2, 16);
    float p1 = a1 * s1;
    float p2 = a2 * s2;
    float t1 = shflx(p1, 8);     // lanes 8-15 <- i*g
    float t2 = shflx(p2, 8);     // lanes 8-13 <- i*g

    // state owners: lanes 8-15 hold a1=f, s1=o
    c1 = fmaf(a1, c1, t1);
    float h1v = s1 * tanha(c1);
    float x2v = tanha(h1v);

    // lanes 8-13 hold a2=f2, s2=o2
    c2 = en * fmaf(a2, c2, t2);
    float h2v = s2 * tanha(c2);

    if (lane >= 8 && lane < 16) {
        shs[WR][lane - 8] = h1v;   // h1 slot (lane-8)
        shs[WR][lane]     = x2v;   // x2 slot 8+(lane-8)
    }
    if (lane >= 8 && lane < 14) shs[WR][8 + lane] = h2v;   // h2 slot 16+(lane-8)
    __syncwarp();
}

// ============================================================================
// fused producer/consumer kernel: 1 block = 1 batch element, 2 warps.
// ============================================================================
__global__ void __launch_bounds__(64)
fused_pc(const float* __restrict__ x,
         const float* __restrict__ W_ih1,
         const float* __restrict__ W_hh1,
         const float* __restrict__ b_ih1,
         const float* __restrict__ b_hh1,
         const float* __restrict__ W_ih2,
         const float* __restrict__ W_hh2,
         const float* __restrict__ b_ih2,
         const float* __restrict__ b_hh2,
         const float* __restrict__ W_fc,
         const float* __restrict__ b_fc,
         float* __restrict__ out) {
    __shared__ __align__(16) float sgate[2][CT][16][2];  // [t][l][k]: gate = k*16+l
    __shared__ __align__(16) float sx[2][CT][FEAT];      // x staging (cp.async)
    __shared__ __align__(16) float shs[2][24];           // h1/x2/h2 slabs

    int tid  = threadIdx.x;
    int lane = tid & 31;
    int wid  = tid >> 5;
    int b    = blockIdx.x;

    if (wid == 1) {
        // ======================= PRODUCER (R7: weights in regs) ==============
        int l = lane & 15, h = lane >> 4;
        int gA = l, gB = l + 16;
        float cmA = 0.5f;                     // gates 0..15: sigmoid
        float cmB = (l < 8) ? 1.0f : 0.5f;    // 16..23 tanh, 24..31 sigmoid

        u64 wA[FEAT / 2], wB[FEAT / 2];
        {
            const u64* wra = reinterpret_cast<const u64*>(W_ih1 + gA * FEAT);
            const u64* wrb = reinterpret_cast<const u64*>(W_ih1 + gB * FEAT);
#pragma unroll
            for (int p = 0; p < FEAT / 2; p++) {
                wA[p] = scale2(wra[p], cmA);
                wB[p] = scale2(wrb[p], cmB);
            }
        }
        float bA = cmA * (b_ih1[gA] + b_hh1[gA]);
        float bB = cmB * (b_ih1[gB] + b_hh1[gB]);

        const float4* xb = reinterpret_cast<const float4*>(x + (size_t)b * T_STEPS * FEAT);
        uint32_t sx0 = smem_u32(&sx[0][0][0]);
        uint32_t sx1 = smem_u32(&sx[1][0][0]);

        // issue chunks 0,1
#pragma unroll
        for (int i = 0; i < 4; i++) {
            int s = lane + 32 * i;
            if (s < SITES) cp_async16(sx0 + 16 * s, xb + s);
        }
        cp_commit();
#pragma unroll
        for (int i = 0; i < 4; i++) {
            int s = lane + 32 * i;
            if (s < SITES) cp_async16(sx1 + 16 * s, xb + SITES + s);
        }
        cp_commit();
        cp_wait<1>();
        __syncwarp();

        // gates chunk 0
        {
#pragma unroll
            for (int p = 0; p < 5; p++) {
                int r = 2 * p + h;
                const ulonglong2* xr = reinterpret_cast<const ulonglong2*>(&sx[0][r][0]);
                u64 a0 = pack2(bA, 0.f), a1 = 0ull;
                u64 b0 = pack2(bB, 0.f), b1 = 0ull;
#pragma unroll
                for (int q = 0; q < FEAT / 4; q++) {
                    ulonglong2 v = xr[q];
                    a0 = fma2(wA[2 * q],     v.x, a0);
                    a1 = fma2(wA[2 * q + 1], v.y, a1);
                    b0 = fma2(wB[2 * q],     v.x, b0);
                    b1 = fma2(wB[2 * q + 1], v.y, b1);
                }
                *reinterpret_cast<u64*>(&sgate[0][r][l][0]) =
                    pack2(hadd2(add2(a0, a1)), hadd2(add2(b0, b1)));
            }
        }
        BAR64();

#pragma unroll 1
        for (int c = 0; c < NCHUNK; c++) {
            if (c + 1 < NCHUNK) {
                int c2i = (c + 2 < NCHUNK) ? c + 2 : NCHUNK - 1;
                uint32_t dst = (c & 1) ? sx1 : sx0;
#pragma unroll
                for (int i = 0; i < 4; i++) {
                    int s = lane + 32 * i;
                    if (s < SITES) cp_async16(dst + 16 * s, xb + c2i * SITES + s);
                }
                cp_commit();
                cp_wait<1>();      // chunk c+1 resident
                __syncwarp();

                float (*dstg)[16][2] = sgate[(c + 1) & 1];
                const float (*src)[FEAT] = sx[(c + 1) & 1];
#pragma unroll
                for (int p = 0; p < 5; p++) {
                    int r = 2 * p + h;
                    const ulonglong2* xr = reinterpret_cast<const ulonglong2*>(&src[r][0]);
                    u64 a0 = pack2(bA, 0.f), a1 = 0ull;
                    u64 b0 = pack2(bB, 0.f), b1 = 0ull;
#pragma unroll
                    for (int q = 0; q < FEAT / 4; q++) {
                        ulonglong2 v = xr[q];
                        a0 = fma2(wA[2 * q],     v.x, a0);
                        a1 = fma2(wA[2 * q + 1], v.y, a1);
                        b0 = fma2(wB[2 * q],     v.x, b0);
                        b1 = fma2(wB[2 * q + 1], v.y, b1);
                    }
                    *reinterpret_cast<u64*>(&dstg[r][l][0]) =
                        pack2(hadd2(add2(a0, a1)), hadd2(add2(b0, b1)));
                }
            }
            BAR64();
        }
        cp_wait<0>();
    } else {
        // ======================= CONSUMER =======================
        // layer1 constants (quarters): tanh for g-quarter = lanes 16-23
        bool t1c = ((lane >> 3) == 2);
        float cm1 = t1c ? 1.f : 0.5f, cn1 = t1c ? 1.f : 0.5f, ca1 = t1c ? 0.f : 0.5f;
        // layer2 quarter-aligned lanes: valid = (lane&7)<6, lane<30
        bool v2 = ((lane & 7) < 6) && (lane < 30);
        int g2i = lane - 2 * (lane >> 3);           // gate index when valid
        bool t2c = (lane >= 16 && lane < 22);       // g-quarter (tanh)
        float cm2 = t2c ? 1.f : 0.5f, cn2 = t2c ? 1.f : 0.5f, ca2 = t2c ? 0.f : 0.5f;

        u64 w1p[H1 / 2];
#pragma unroll
        for (int j = 0; j < H1 / 2; j++)
            w1p[j] = pack2(cm1 * W_hh1[lane * H1 + 2 * j], cm1 * W_hh1[lane * H1 + 2 * j + 1]);

        u64 wi2p[H1 / 2], wh2p[H2 / 2], bias2p = 0ull;
#pragma unroll
        for (int j = 0; j < H1 / 2; j++) wi2p[j] = 0ull;
#pragma unroll
        for (int j = 0; j < H2 / 2; j++) wh2p[j] = 0ull;
        if (v2) {
#pragma unroll
            for (int j = 0; j < H1 / 2; j++)
                wi2p[j] = pack2(cm2 * W_ih2[g2i * H1 + 2 * j], cm2 * W_ih2[g2i * H1 + 2 * j + 1]);
#pragma unroll
            for (int j = 0; j < H2 / 2; j++)
                wh2p[j] = pack2(cm2 * W_hh2[g2i * H2 + 2 * j], cm2 * W_hh2[g2i * H2 + 2 * j + 1]);
            bias2p = pack2(cm2 * (b_ih2[g2i] + b_hh2[g2i]), 0.f);
        }

        if (lane < 24) shs[1][lane] = 0.f;
        float c1 = 0.f, c2 = 0.f;
        BAR64();

        int gidx = (lane & 15) * 2 + (lane >> 4);   // packed-ring offset for this gate

#pragma unroll 1
        for (int c = 0; c < NCHUNK; c++) {
            const float* gr = &sgate[c & 1][0][0][0];
            float en0 = (c == 0) ? 0.f : 1.f;

            rec_step<1>(en0, lane, gr[0 * 32 + gidx], shs, w1p, wi2p, wh2p, bias2p,
                        cn1, ca1, cn2, ca2, c1, c2);
            rec_step<0>(1.f, lane, gr[1 * 32 + gidx], shs, w1p, wi2p, wh2p, bias2p,
                        cn1, ca1, cn2, ca2, c1, c2);
            rec_step<1>(1.f, lane, gr[2 * 32 + gidx], shs, w1p, wi2p, wh2p, bias2p,
                        cn1, ca1, cn2, ca2, c1, c2);
            rec_step<0>(1.f, lane, gr[3 * 32 + gidx], shs, w1p, wi2p, wh2p, bias2p,
                        cn1, ca1, cn2, ca2, c1, c2);
            rec_step<1>(1.f, lane, gr[4 * 32 + gidx], shs, w1p, wi2p, wh2p, bias2p,
                        cn1, ca1, cn2, ca2, c1, c2);
            rec_step<0>(1.f, lane, gr[5 * 32 + gidx], shs, w1p, wi2p, wh2p, bias2p,
                        cn1, ca1, cn2, ca2, c1, c2);
            rec_step<1>(1.f, lane, gr[6 * 32 + gidx], shs, w1p, wi2p, wh2p, bias2p,
                        cn1, ca1, cn2, ca2, c1, c2);
            rec_step<0>(1.f, lane, gr[7 * 32 + gidx], shs, w1p, wi2p, wh2p, bias2p,
                        cn1, ca1, cn2, ca2, c1, c2);
            rec_step<1>(1.f, lane, gr[8 * 32 + gidx], shs, w1p, wi2p, wh2p, bias2p,
                        cn1, ca1, cn2, ca2, c1, c2);
            rec_step<0>(1.f, lane, gr[9 * 32 + gidx], shs, w1p, wi2p, wh2p, bias2p,
                        cn1, ca1, cn2, ca2, c1, c2);
            BAR64();
        }

        // ---- epilogue: layer2(999) from shs[1] (x2(999), h2(998)) ----
        const ulonglong2* hp = reinterpret_cast<const ulonglong2*>(&shs[1][0]);
        ulonglong2 x01 = hp[2], x23 = hp[3], h2a = hp[4];
        u64 h2b = reinterpret_cast<const u64*>(&shs[1][0])[10];

        u64 P = fma2(x01.x, wi2p[0], bias2p);
        u64 Q = mul2(x01.y, wi2p[1]);
        P = fma2(x23.x, wi2p[2], P);
        Q = fma2(x23.y, wi2p[3], Q);
        P = fma2(h2a.x, wh2p[0], P);
        Q = fma2(h2a.y, wh2p[1], Q);
        P = fma2(h2b,   wh2p[2], P);
        float g2 = hadd2(add2(P, Q));

        float a2 = fmaf(cn2, tanha(g2), ca2);
        float s2 = shflx(a2, 16);
        float p2 = a2 * s2;
        float t2 = shflx(p2, 8);
        c2 = fmaf(a2, c2, t2);                 // lanes 8-13
        float tx = tanha(s2 * tanha(c2));      // tanh(h2(999)) at lanes 8-13

        float s = b_fc[0];
#pragma unroll
        for (int j = 0; j < H2; j++)
            s = fmaf(shflf(tx, 8 + j), W_fc[j], s);
        if (lane == 0)
            out[b] = fmaf(0.5f, tanha(0.5f * s), 0.5f);
    }
}

// ============================================================================
extern "C" void kernel_launch(void* const* d_in, const int* in_sizes, int n_in,
                              void* d_out, int out_size) {
    const float* x     = (const float*)d_in[0];
    const float* W_ih1 = (const float*)d_in[1];
    const float* W_hh1 = (const float*)d_in[2];
    const float* b_ih1 = (const float*)d_in[3];
    const float* b_hh1 = (const float*)d_in[4];
    const float* W_ih2 = (const float*)d_in[5];
    const float* W_hh2 = (const float*)d_in[6];
    const float* b_ih2 = (const float*)d_in[7];
    const float* b_hh2 = (const float*)d_in[8];
    const float* W_fc  = (const float*)d_in[9];
    const float* b_fc  = (const float*)d_in[10];
    float* out = (float*)d_out;

    fused_pc<<<BATCH, 64>>>(x, W_ih1, W_hh1, b_ih1, b_hh1,
                            W_ih2, W_hh2, b_ih2, b_hh2, W_fc, b_fc, out);
}